// round 2
// baseline (speedup 1.0000x reference)
#include <cuda_runtime.h>
#include <cstdint>

// ShapeNet class -> contiguous part-id range starts
__constant__ int c_starts[17] = {0, 4, 6, 8, 12, 16, 19, 22, 24, 28, 30, 36, 38, 41, 44, 47, 50};

// Scratch: per-(b, part) counters. B<=64, C<=64 -> 4096 entries each.
#define MAX_BC 4096
__device__ unsigned g_inter[MAX_BC];
__device__ unsigned g_pred[MAX_BC];
__device__ unsigned g_gt[MAX_BC];

__global__ void zero_counters_kernel(int bc) {
    int i = blockIdx.x * blockDim.x + threadIdx.x;
    if (i < bc) {
        g_inter[i] = 0u;
        g_pred[i]  = 0u;
        g_gt[i]    = 0u;
    }
}

// grid: (chunks, B). Each block handles N/chunks points of batch row b.
template <int TPB>
__global__ void __launch_bounds__(TPB)
seg_hist_kernel(const float* __restrict__ logits,
                const int* __restrict__ targets,
                const int* __restrict__ labels,
                float* __restrict__ pred_out,   // may be null
                int C, int N)
{
    const int b = blockIdx.y;
    int cls = labels[b];
    cls = min(max(cls, 0), 15);            // defensive clamp
    const int start = c_starts[cls];
    const int width = c_starts[cls + 1] - start;

    __shared__ unsigned s_pred[64], s_gt[64], s_inter[64];
    for (int i = threadIdx.x; i < 64; i += TPB) {
        s_pred[i] = 0u; s_gt[i] = 0u; s_inter[i] = 0u;
    }
    __syncthreads();

    const float* __restrict__ lb = logits + (size_t)b * C * N;
    const int* __restrict__ tb = targets + (size_t)b * N;
    float* __restrict__ pb = pred_out ? (pred_out + (size_t)b * N) : nullptr;

    const int pts = N / gridDim.x;          // N chosen multiple of chunks*TPB
    const int n0 = blockIdx.x * pts;
    const int lane = threadIdx.x & 31;
    const unsigned FULL = 0xFFFFFFFFu;

    for (int n = n0 + threadIdx.x; n < n0 + pts; n += TPB) {
        // masked argmax over the contiguous valid channel range (2..6 channels)
        float best = lb[(size_t)start * N + n];
        int bestc = start;
        #pragma unroll 6
        for (int j = 1; j < width; j++) {
            float v = lb[(size_t)(start + j) * N + n];
            if (v > best) { best = v; bestc = start + j; }
        }
        int tgt = tb[n];
        tgt = min(max(tgt, 0), C - 1);      // defensive clamp
        const bool match = (bestc == tgt);

        if (pb) pb[n] = (float)bestc;

        // pred / inter histograms: width <= 6 uniform bins per block,
        // warp-aggregate via ballot so only lane 0 touches smem atomics.
        #pragma unroll 6
        for (int j = 0; j < width; j++) {
            unsigned mp = __ballot_sync(FULL, bestc == start + j);
            unsigned mi = __ballot_sync(FULL, match && (bestc == start + j));
            if (lane == 0) {
                if (mp) atomicAdd(&s_pred[start + j], (unsigned)__popc(mp));
                if (mi) atomicAdd(&s_inter[start + j], (unsigned)__popc(mi));
            }
        }
        // gt histogram: targets span all bins -> match_any leader aggregation
        unsigned grp = __match_any_sync(FULL, tgt);
        if (lane == (__ffs(grp) - 1)) {
            atomicAdd(&s_gt[tgt], (unsigned)__popc(grp));
        }
    }
    __syncthreads();

    for (int i = threadIdx.x; i < C && i < 64; i += TPB) {
        if (s_pred[i])  atomicAdd(&g_pred[b * C + i],  s_pred[i]);
        if (s_gt[i])    atomicAdd(&g_gt[b * C + i],    s_gt[i]);
        if (s_inter[i]) atomicAdd(&g_inter[b * C + i], s_inter[i]);
    }
}

// One block, one thread per batch row; deterministic reduction.
__global__ void finalize_kernel(const int* __restrict__ labels,
                                float* __restrict__ mean_out,
                                int B, int C)
{
    __shared__ float s_iou[128];
    const int b = threadIdx.x;
    float v = 0.0f;
    if (b < B) {
        int cls = labels[b];
        cls = min(max(cls, 0), 15);
        const int start = c_starts[cls];
        const int end = c_starts[cls + 1];
        float acc = 0.0f;
        for (int p = start; p < end; p++) {
            float inter = (float)g_inter[b * C + p];
            float uni = (float)g_pred[b * C + p] + (float)g_gt[b * C + p] - inter;
            float iou = (uni == 0.0f) ? 1.0f : (inter / fmaxf(uni, 1.0f));
            acc += iou;
        }
        v = acc / (float)(end - start);
    }
    if (b < 128) s_iou[b] = v;
    __syncthreads();
    if (threadIdx.x == 0) {
        float total = 0.0f;
        for (int i = 0; i < B; i++) total += s_iou[i];
        if (mean_out) *mean_out = total / (float)B;
    }
}

extern "C" void kernel_launch(void* const* d_in, const int* in_sizes, int n_in,
                              void* d_out, int out_size)
{
    // Identify inputs by element count, robust to ordering:
    //   class_labels: smallest (B) ; logits: largest (B*C*N) ; targets: middle (B*N)
    int i_log = 0, i_tgt = 1, i_lab = 2;
    for (int i = 0; i < 3; i++) {
        if (in_sizes[i] > in_sizes[i_log]) i_log = i;
        if (in_sizes[i] < in_sizes[i_lab]) i_lab = i;
    }
    i_tgt = 3 - i_log - i_lab;

    const float* logits  = (const float*)d_in[i_log];
    const int*   targets = (const int*)d_in[i_tgt];
    const int*   labels  = (const int*)d_in[i_lab];

    const int B  = in_sizes[i_lab];
    const int BN = in_sizes[i_tgt];
    const int N  = BN / B;
    const int C  = in_sizes[i_log] / BN;

    float* out = (float*)d_out;
    float* mean_out = nullptr;
    float* pred_out = nullptr;
    if (out_size >= BN + 1)      { mean_out = out; pred_out = out + 1; }
    else if (out_size == BN)     { pred_out = out; }
    else                         { mean_out = out; }

    const int bc = B * C;
    zero_counters_kernel<<<(bc + 255) / 256, 256>>>(bc);

    constexpr int TPB = 256;
    int chunks = 32;                       // N=65536 -> 2048 pts/block, 8 pts/thread
    while (chunks > 1 && (N % (chunks * TPB) != 0)) chunks >>= 1;
    if (N % TPB != 0) chunks = 1;          // ultra-safe fallback
    dim3 grid(chunks, B);
    seg_hist_kernel<TPB><<<grid, TPB>>>(logits, targets, labels, pred_out, C, N);

    finalize_kernel<<<1, 128>>>(labels, mean_out, B, C);
}

// round 4
// speedup vs baseline: 2.3109x; 2.3109x over previous
#include <cuda_runtime.h>
#include <cstdint>

__constant__ int c_starts[17] = {0, 4, 6, 8, 12, 16, 19, 22, 24, 28, 30, 36, 38, 41, 44, 47, 50};

#define MAX_BC 4096
__device__ unsigned g_inter[MAX_BC];
__device__ unsigned g_pred[MAX_BC];
__device__ unsigned g_gt[MAX_BC];

// ---------------- fast path: width-specialized, vectorized, register histograms -------------
template <int W, int TPB>
__device__ __forceinline__ void run_body(const float* __restrict__ lb,
                                         const int* __restrict__ tb,
                                         float* __restrict__ pb,
                                         int start, int N, int iters, int b, int C)
{
    __shared__ unsigned s_gt[8], s_pred[8], s_inter[8];
    if (threadIdx.x < 8) { s_gt[threadIdx.x] = 0u; s_pred[threadIdx.x] = 0u; s_inter[threadIdx.x] = 0u; }
    __syncthreads();

    unsigned long long acc_p = 0ull, acc_i = 0ull;
    const int tid = threadIdx.x;
    const int base_n = blockIdx.x * (TPB * 4 * iters);

    for (int it = 0; it < iters; ++it) {
        const int n = base_n + (it * TPB + tid) * 4;
        const float* p0 = lb + (size_t)start * N + n;
        float4 v[W];
#pragma unroll
        for (int j = 0; j < W; ++j)
            v[j] = *reinterpret_cast<const float4*>(p0 + (size_t)j * N);
        const int4 t4 = *reinterpret_cast<const int4*>(tb + n);
        const int tarr[4] = {t4.x, t4.y, t4.z, t4.w};

#pragma unroll
        for (int e = 0; e < 4; ++e) {
            float best = reinterpret_cast<const float*>(&v[0])[e];
            int bestc = 0;
#pragma unroll
            for (int j = 1; j < W; ++j) {
                float val = reinterpret_cast<const float*>(&v[j])[e];
                if (val > best) { best = val; bestc = j; }   // strict > keeps first index on ties
            }
            const unsigned bt = (unsigned)(tarr[e] - start);
            const unsigned long long one = 1ull << (bestc * 10);
            acc_p += one;
            if (bt == (unsigned)bestc) acc_i += one;          // intersection
            if (bt < (unsigned)W) atomicAdd(&s_gt[bt], 1u);   // ~W/50 of lanes active
            pb[n + e] = (float)(bestc + start);               // scalar store: pb may be 4B-offset
        }
    }

    // warp-level reduction of packed accumulators (per-warp bin sums <= 512 < 1024)
#pragma unroll
    for (int off = 16; off; off >>= 1) {
        acc_p += __shfl_down_sync(0xFFFFFFFFu, acc_p, off);
        acc_i += __shfl_down_sync(0xFFFFFFFFu, acc_i, off);
    }
    if ((threadIdx.x & 31) == 0) {
#pragma unroll
        for (int j = 0; j < W; ++j) {
            const unsigned cp = (unsigned)((acc_p >> (10 * j)) & 1023u);
            const unsigned ci = (unsigned)((acc_i >> (10 * j)) & 1023u);
            if (cp) atomicAdd(&s_pred[j], cp);
            if (ci) atomicAdd(&s_inter[j], ci);
        }
    }
    __syncthreads();
    if (threadIdx.x < W) {
        const int g = b * C + start + threadIdx.x;
        const unsigned sp = s_pred[threadIdx.x], si = s_inter[threadIdx.x], sg = s_gt[threadIdx.x];
        if (sp) atomicAdd(&g_pred[g], sp);
        if (si) atomicAdd(&g_inter[g], si);
        if (sg) atomicAdd(&g_gt[g], sg);
    }
}

template <int TPB>
__global__ void __launch_bounds__(TPB)
seg_hist_fast(const float* __restrict__ logits,
              const int* __restrict__ targets,
              const int* __restrict__ labels,
              float* __restrict__ pred_out,
              int C, int N, int iters)
{
    const int b = blockIdx.y;
    int cls = labels[b];
    cls = min(max(cls, 0), 15);
    const int start = c_starts[cls];
    const int width = c_starts[cls + 1] - start;

    const float* lb = logits + (size_t)b * C * N;
    const int* tb = targets + (size_t)b * N;
    float* pb = pred_out + (size_t)b * N;

    switch (width) {
        case 2: run_body<2, TPB>(lb, tb, pb, start, N, iters, b, C); break;
        case 3: run_body<3, TPB>(lb, tb, pb, start, N, iters, b, C); break;
        case 4: run_body<4, TPB>(lb, tb, pb, start, N, iters, b, C); break;
        default: run_body<6, TPB>(lb, tb, pb, start, N, iters, b, C); break;
    }
}

// ---------------- fallback (generic sizes) ----------------
template <int TPB>
__global__ void __launch_bounds__(TPB)
seg_hist_generic(const float* __restrict__ logits,
                 const int* __restrict__ targets,
                 const int* __restrict__ labels,
                 float* __restrict__ pred_out,
                 int C, int N)
{
    const int b = blockIdx.y;
    int cls = labels[b];
    cls = min(max(cls, 0), 15);
    const int start = c_starts[cls];
    const int width = c_starts[cls + 1] - start;

    __shared__ unsigned s_pred[8], s_gt[8], s_inter[8];
    if (threadIdx.x < 8) { s_pred[threadIdx.x] = 0u; s_gt[threadIdx.x] = 0u; s_inter[threadIdx.x] = 0u; }
    __syncthreads();

    const float* lb = logits + (size_t)b * C * N;
    const int* tb = targets + (size_t)b * N;
    float* pb = pred_out + (size_t)b * N;

    const int pts = (N + gridDim.x - 1) / gridDim.x;
    const int n0 = blockIdx.x * pts;
    const int n1 = min(n0 + pts, N);

    for (int n = n0 + threadIdx.x; n < n1; n += TPB) {
        float best = lb[(size_t)start * N + n];
        int bestc = 0;
        for (int j = 1; j < width; j++) {
            float v = lb[(size_t)(start + j) * N + n];
            if (v > best) { best = v; bestc = j; }
        }
        const unsigned bt = (unsigned)(tb[n] - start);
        atomicAdd(&s_pred[bestc], 1u);
        if (bt == (unsigned)bestc) atomicAdd(&s_inter[bestc], 1u);
        if (bt < (unsigned)width) atomicAdd(&s_gt[bt], 1u);
        pb[n] = (float)(bestc + start);
    }
    __syncthreads();
    if (threadIdx.x < width) {
        const int g = b * C + start + threadIdx.x;
        if (s_pred[threadIdx.x])  atomicAdd(&g_pred[g],  s_pred[threadIdx.x]);
        if (s_gt[threadIdx.x])    atomicAdd(&g_gt[g],    s_gt[threadIdx.x]);
        if (s_inter[threadIdx.x]) atomicAdd(&g_inter[g], s_inter[threadIdx.x]);
    }
}

// One block; computes mean IoU and re-zeroes the (in-range-only) counters so
// every graph replay starts from a clean state.
__global__ void finalize_kernel(const int* __restrict__ labels,
                                float* __restrict__ mean_out,
                                int B, int C)
{
    __shared__ float s_iou[128];
    const int b = threadIdx.x;
    float v = 0.0f;
    if (b < B) {
        int cls = labels[b];
        cls = min(max(cls, 0), 15);
        const int start = c_starts[cls];
        const int end = c_starts[cls + 1];
        float acc = 0.0f;
        for (int p = start; p < end; p++) {
            const int g = b * C + p;
            const float inter = (float)g_inter[g];
            const float uni = (float)g_pred[g] + (float)g_gt[g] - inter;
            const float iou = (uni == 0.0f) ? 1.0f : (inter / fmaxf(uni, 1.0f));
            acc += iou;
            g_inter[g] = 0u; g_pred[g] = 0u; g_gt[g] = 0u;   // reset for next replay
        }
        v = acc / (float)(end - start);
    }
    if (b < 128) s_iou[b] = v;
    __syncthreads();
    if (threadIdx.x == 0) {
        float total = 0.0f;
        for (int i = 0; i < B; i++) total += s_iou[i];
        if (mean_out) *mean_out = total / (float)B;
    }
}

extern "C" void kernel_launch(void* const* d_in, const int* in_sizes, int n_in,
                              void* d_out, int out_size)
{
    // Identify inputs by element count (labels: B, targets: B*N, logits: B*C*N)
    int i_log = 0, i_lab = 0;
    for (int i = 0; i < 3; i++) {
        if (in_sizes[i] > in_sizes[i_log]) i_log = i;
        if (in_sizes[i] < in_sizes[i_lab]) i_lab = i;
    }
    const int i_tgt = 3 - i_log - i_lab;

    const float* logits  = (const float*)d_in[i_log];
    const int*   targets = (const int*)d_in[i_tgt];
    const int*   labels  = (const int*)d_in[i_lab];

    const int B  = in_sizes[i_lab];
    const int BN = in_sizes[i_tgt];
    const int N  = BN / B;
    const int C  = in_sizes[i_log] / BN;

    float* out = (float*)d_out;
    float* mean_out = nullptr;
    float* pred_out = nullptr;
    if (out_size >= BN + 1)      { mean_out = out; pred_out = out + 1; }
    else if (out_size == BN)     { pred_out = out; }
    else                         { mean_out = out; pred_out = out; }

    constexpr int TPB = 256;
    constexpr int ITERS = 4;                       // 16 points / thread
    const int span = TPB * 4 * ITERS;              // 4096 points / block
    if (pred_out && (N % span) == 0) {
        dim3 grid(N / span, B);
        seg_hist_fast<TPB><<<grid, TPB>>>(logits, targets, labels, pred_out, C, N, ITERS);
    } else {
        dim3 grid(32, B);
        seg_hist_generic<TPB><<<grid, TPB>>>(logits, targets, labels, pred_out, C, N);
    }

    finalize_kernel<<<1, 128>>>(labels, mean_out, B, C);
}

// round 5
// speedup vs baseline: 2.3796x; 1.0297x over previous
#include <cuda_runtime.h>
#include <cstdint>

__constant__ int c_starts[17] = {0, 4, 6, 8, 12, 16, 19, 22, 24, 28, 30, 36, 38, 41, 44, 47, 50};

#define MAX_BC 4096
__device__ unsigned g_inter[MAX_BC];
__device__ unsigned g_pred[MAX_BC];
__device__ unsigned g_gt[MAX_BC];
__device__ unsigned g_done;   // zero-initialized; reset by last block each run

// ---------------- fast path: width-specialized, vectorized, register histograms -------------
template <int W, int TPB>
__device__ __forceinline__ void run_body(const float* __restrict__ lb,
                                         const int* __restrict__ tb,
                                         float* __restrict__ pb,
                                         int start, int N, int iters, int b, int C)
{
    __shared__ unsigned s_gt[8], s_pred[8], s_inter[8];
    if (threadIdx.x < 8) { s_gt[threadIdx.x] = 0u; s_pred[threadIdx.x] = 0u; s_inter[threadIdx.x] = 0u; }
    __syncthreads();

    unsigned long long acc_p = 0ull, acc_i = 0ull;
    const int tid = threadIdx.x;
    const int base_n = blockIdx.x * (TPB * 4 * iters);

    for (int it = 0; it < iters; ++it) {
        const int n = base_n + (it * TPB + tid) * 4;
        const float* p0 = lb + (size_t)start * N + n;
        float4 v[W];
#pragma unroll
        for (int j = 0; j < W; ++j)
            v[j] = *reinterpret_cast<const float4*>(p0 + (size_t)j * N);
        const int4 t4 = *reinterpret_cast<const int4*>(tb + n);
        const int tarr[4] = {t4.x, t4.y, t4.z, t4.w};

#pragma unroll
        for (int e = 0; e < 4; ++e) {
            float best = reinterpret_cast<const float*>(&v[0])[e];
            int bestc = 0;
#pragma unroll
            for (int j = 1; j < W; ++j) {
                float val = reinterpret_cast<const float*>(&v[j])[e];
                if (val > best) { best = val; bestc = j; }   // strict > keeps first index on ties
            }
            const unsigned bt = (unsigned)(tarr[e] - start);
            const unsigned long long one = 1ull << (bestc * 10);
            acc_p += one;
            if (bt == (unsigned)bestc) acc_i += one;          // intersection
            if (bt < (unsigned)W) atomicAdd(&s_gt[bt], 1u);   // ~W/50 of lanes active
            pb[n + e] = (float)(bestc + start);               // scalar store: pb may be 4B-offset
        }
    }

    // warp-level reduction of packed accumulators (per-warp bin sums <= 512 < 1024)
#pragma unroll
    for (int off = 16; off; off >>= 1) {
        acc_p += __shfl_down_sync(0xFFFFFFFFu, acc_p, off);
        acc_i += __shfl_down_sync(0xFFFFFFFFu, acc_i, off);
    }
    if ((threadIdx.x & 31) == 0) {
#pragma unroll
        for (int j = 0; j < W; ++j) {
            const unsigned cp = (unsigned)((acc_p >> (10 * j)) & 1023u);
            const unsigned ci = (unsigned)((acc_i >> (10 * j)) & 1023u);
            if (cp) atomicAdd(&s_pred[j], cp);
            if (ci) atomicAdd(&s_inter[j], ci);
        }
    }
    __syncthreads();
    if (threadIdx.x < W) {
        const int g = b * C + start + threadIdx.x;
        const unsigned sp = s_pred[threadIdx.x], si = s_inter[threadIdx.x], sg = s_gt[threadIdx.x];
        if (sp) atomicAdd(&g_pred[g], sp);
        if (si) atomicAdd(&g_inter[g], si);
        if (sg) atomicAdd(&g_gt[g], sg);
    }
}

template <int TPB>
__global__ void __launch_bounds__(TPB)
seg_hist_fused(const float* __restrict__ logits,
               const int* __restrict__ targets,
               const int* __restrict__ labels,
               float* __restrict__ pred_out,
               float* __restrict__ mean_out,
               int C, int N, int iters, int B, int total_blocks)
{
    const int b = blockIdx.y;
    {
        int cls = labels[b];
        cls = min(max(cls, 0), 15);
        const int start = c_starts[cls];
        const int width = c_starts[cls + 1] - start;

        const float* lb = logits + (size_t)b * C * N;
        const int* tb = targets + (size_t)b * N;
        float* pb = pred_out + (size_t)b * N;

        switch (width) {
            case 2: run_body<2, TPB>(lb, tb, pb, start, N, iters, b, C); break;
            case 3: run_body<3, TPB>(lb, tb, pb, start, N, iters, b, C); break;
            case 4: run_body<4, TPB>(lb, tb, pb, start, N, iters, b, C); break;
            default: run_body<6, TPB>(lb, tb, pb, start, N, iters, b, C); break;
        }
    }

    // ---- last-block finalize (fused tail; avoids a second launch) ----
    __shared__ unsigned s_last;
    if (threadIdx.x == 0) {
        __threadfence();                       // publish this block's g_* atomics
        s_last = (atomicAdd(&g_done, 1u) == (unsigned)(total_blocks - 1)) ? 1u : 0u;
    }
    __syncthreads();
    if (!s_last) return;

    __shared__ float s_iou[64];
    const int t = threadIdx.x;
    float v = 0.0f;
    if (t < B) {
        int cls = labels[t];
        cls = min(max(cls, 0), 15);
        const int start = c_starts[cls];
        const int width = c_starts[cls + 1] - start;

        // batch all (<=6 x 3) counter loads with clamped indices for full MLP overlap
        unsigned ci[6], cp[6], cg[6];
#pragma unroll
        for (int j = 0; j < 6; ++j) {
            const int p = start + min(j, width - 1);
            const int g = t * C + p;
            ci[j] = g_inter[g];
            cp[j] = g_pred[g];
            cg[j] = g_gt[g];
        }
        float acc = 0.0f;
#pragma unroll
        for (int j = 0; j < 6; ++j) {
            if (j < width) {
                const float inter = (float)ci[j];
                const float uni = (float)cp[j] + (float)cg[j] - inter;
                acc += (uni == 0.0f) ? 1.0f : (inter / fmaxf(uni, 1.0f));
            }
        }
        v = acc / (float)width;

        // reset counters (only in-range bins are ever written) for next graph replay
#pragma unroll
        for (int j = 0; j < 6; ++j) {
            if (j < width) {
                const int g = t * C + start + j;
                g_inter[g] = 0u; g_pred[g] = 0u; g_gt[g] = 0u;
            }
        }
    }
    if (t < 64) s_iou[t] = v;
    __syncthreads();
    if (t == 0) {
        float total = 0.0f;
        for (int i = 0; i < B; i++) total += s_iou[i];
        if (mean_out) *mean_out = total / (float)B;
        g_done = 0u;                            // reset flag for next replay
        __threadfence();
    }
}

// ---------------- fallback (generic sizes): separate kernels ----------------
template <int TPB>
__global__ void __launch_bounds__(TPB)
seg_hist_generic(const float* __restrict__ logits,
                 const int* __restrict__ targets,
                 const int* __restrict__ labels,
                 float* __restrict__ pred_out,
                 int C, int N)
{
    const int b = blockIdx.y;
    int cls = labels[b];
    cls = min(max(cls, 0), 15);
    const int start = c_starts[cls];
    const int width = c_starts[cls + 1] - start;

    __shared__ unsigned s_pred[8], s_gt[8], s_inter[8];
    if (threadIdx.x < 8) { s_pred[threadIdx.x] = 0u; s_gt[threadIdx.x] = 0u; s_inter[threadIdx.x] = 0u; }
    __syncthreads();

    const float* lb = logits + (size_t)b * C * N;
    const int* tb = targets + (size_t)b * N;
    float* pb = pred_out + (size_t)b * N;

    const int pts = (N + gridDim.x - 1) / gridDim.x;
    const int n0 = blockIdx.x * pts;
    const int n1 = min(n0 + pts, N);

    for (int n = n0 + threadIdx.x; n < n1; n += TPB) {
        float best = lb[(size_t)start * N + n];
        int bestc = 0;
        for (int j = 1; j < width; j++) {
            float v = lb[(size_t)(start + j) * N + n];
            if (v > best) { best = v; bestc = j; }
        }
        const unsigned bt = (unsigned)(tb[n] - start);
        atomicAdd(&s_pred[bestc], 1u);
        if (bt == (unsigned)bestc) atomicAdd(&s_inter[bestc], 1u);
        if (bt < (unsigned)width) atomicAdd(&s_gt[bt], 1u);
        pb[n] = (float)(bestc + start);
    }
    __syncthreads();
    if (threadIdx.x < width) {
        const int g = b * C + start + threadIdx.x;
        if (s_pred[threadIdx.x])  atomicAdd(&g_pred[g],  s_pred[threadIdx.x]);
        if (s_gt[threadIdx.x])    atomicAdd(&g_gt[g],    s_gt[threadIdx.x]);
        if (s_inter[threadIdx.x]) atomicAdd(&g_inter[g], s_inter[threadIdx.x]);
    }
}

__global__ void finalize_kernel(const int* __restrict__ labels,
                                float* __restrict__ mean_out,
                                int B, int C)
{
    __shared__ float s_iou[128];
    const int b = threadIdx.x;
    float v = 0.0f;
    if (b < B) {
        int cls = labels[b];
        cls = min(max(cls, 0), 15);
        const int start = c_starts[cls];
        const int end = c_starts[cls + 1];
        float acc = 0.0f;
        for (int p = start; p < end; p++) {
            const int g = b * C + p;
            const float inter = (float)g_inter[g];
            const float uni = (float)g_pred[g] + (float)g_gt[g] - inter;
            const float iou = (uni == 0.0f) ? 1.0f : (inter / fmaxf(uni, 1.0f));
            acc += iou;
            g_inter[g] = 0u; g_pred[g] = 0u; g_gt[g] = 0u;
        }
        v = acc / (float)(end - start);
    }
    if (b < 128) s_iou[b] = v;
    __syncthreads();
    if (threadIdx.x == 0) {
        float total = 0.0f;
        for (int i = 0; i < B; i++) total += s_iou[i];
        if (mean_out) *mean_out = total / (float)B;
    }
}

extern "C" void kernel_launch(void* const* d_in, const int* in_sizes, int n_in,
                              void* d_out, int out_size)
{
    // Identify inputs by element count (labels: B, targets: B*N, logits: B*C*N)
    int i_log = 0, i_lab = 0;
    for (int i = 0; i < 3; i++) {
        if (in_sizes[i] > in_sizes[i_log]) i_log = i;
        if (in_sizes[i] < in_sizes[i_lab]) i_lab = i;
    }
    const int i_tgt = 3 - i_log - i_lab;

    const float* logits  = (const float*)d_in[i_log];
    const int*   targets = (const int*)d_in[i_tgt];
    const int*   labels  = (const int*)d_in[i_lab];

    const int B  = in_sizes[i_lab];
    const int BN = in_sizes[i_tgt];
    const int N  = BN / B;
    const int C  = in_sizes[i_log] / BN;

    float* out = (float*)d_out;
    float* mean_out = nullptr;
    float* pred_out = nullptr;
    if (out_size >= BN + 1)      { mean_out = out; pred_out = out + 1; }
    else if (out_size == BN)     { pred_out = out; }
    else                         { mean_out = out; pred_out = out; }

    constexpr int TPB = 256;
    constexpr int ITERS = 4;                       // 16 points / thread
    const int span = TPB * 4 * ITERS;              // 4096 points / block
    if (pred_out && (N % span) == 0 && B <= 64) {
        dim3 grid(N / span, B);
        const int total_blocks = (N / span) * B;
        seg_hist_fused<TPB><<<grid, TPB>>>(logits, targets, labels, pred_out,
                                           mean_out, C, N, ITERS, B, total_blocks);
    } else {
        dim3 grid(32, B);
        seg_hist_generic<TPB><<<grid, TPB>>>(logits, targets, labels, pred_out, C, N);
        finalize_kernel<<<1, 128>>>(labels, mean_out, B, C);
    }
}

// round 6
// speedup vs baseline: 2.5263x; 1.0617x over previous
#include <cuda_runtime.h>
#include <cstdint>

__constant__ int c_starts[17] = {0, 4, 6, 8, 12, 16, 19, 22, 24, 28, 30, 36, 38, 41, 44, 47, 50};

#define MAX_BC 4096
__device__ unsigned g_inter[MAX_BC];
__device__ unsigned g_pred[MAX_BC];
__device__ unsigned g_gt[MAX_BC];
__device__ unsigned g_done;   // zero-initialized; reset by last block each run

// ---------------- fast path: width-specialized, vectorized, all-register histograms ---------
// Per-thread packed 64-bit accumulators: 6 bins x 10 bits. Per-warp bin sums <= 32*16 = 512.
template <int W, int TPB, int ITERS>
__device__ __forceinline__ void run_body(const float* __restrict__ lb,
                                         const int* __restrict__ tb,
                                         float* __restrict__ pb,
                                         int start, int N, int b, int C)
{
    __shared__ unsigned s_gt[8], s_pred[8], s_inter[8];
    if (threadIdx.x < 8) { s_gt[threadIdx.x] = 0u; s_pred[threadIdx.x] = 0u; s_inter[threadIdx.x] = 0u; }

    unsigned long long acc_p = 0ull, acc_i = 0ull, acc_g = 0ull;
    const int tid = threadIdx.x;
    const int base_n = blockIdx.x * (TPB * 4 * ITERS);
    const float* __restrict__ l0 = lb + (size_t)start * N;

#pragma unroll
    for (int it = 0; it < ITERS; ++it) {
        const int n = base_n + (it * TPB + tid) * 4;
        float4 v[W];
#pragma unroll
        for (int j = 0; j < W; ++j)
            v[j] = *reinterpret_cast<const float4*>(l0 + (size_t)j * N + n);
        const int4 t4 = *reinterpret_cast<const int4*>(tb + n);
        const int tarr[4] = {t4.x, t4.y, t4.z, t4.w};

#pragma unroll
        for (int e = 0; e < 4; ++e) {
            float best = reinterpret_cast<const float*>(&v[0])[e];
            int bestc = 0;
#pragma unroll
            for (int j = 1; j < W; ++j) {
                float val = reinterpret_cast<const float*>(&v[j])[e];
                if (val > best) { best = val; bestc = j; }   // strict > keeps first index on ties
            }
            const unsigned bt = (unsigned)(tarr[e] - start);
            const unsigned long long one = 1ull << (bestc * 10);
            acc_p += one;
            if (bt == (unsigned)bestc) acc_i += one;                 // intersection
            if (bt < (unsigned)W) acc_g += 1ull << (bt * 10);        // in-range gt count
            pb[n + e] = (float)(bestc + start);                      // pb may be 4B-offset
        }
    }

    // warp-level reduction of packed accumulators
#pragma unroll
    for (int off = 16; off; off >>= 1) {
        acc_p += __shfl_down_sync(0xFFFFFFFFu, acc_p, off);
        acc_i += __shfl_down_sync(0xFFFFFFFFu, acc_i, off);
        acc_g += __shfl_down_sync(0xFFFFFFFFu, acc_g, off);
    }
    __syncthreads();                          // s_* zeroed before any atomics land
    if ((threadIdx.x & 31) == 0) {
#pragma unroll
        for (int j = 0; j < W; ++j) {
            const unsigned cp = (unsigned)((acc_p >> (10 * j)) & 1023u);
            const unsigned ci = (unsigned)((acc_i >> (10 * j)) & 1023u);
            const unsigned cg = (unsigned)((acc_g >> (10 * j)) & 1023u);
            if (cp) atomicAdd(&s_pred[j], cp);
            if (ci) atomicAdd(&s_inter[j], ci);
            if (cg) atomicAdd(&s_gt[j], cg);
        }
    }
    __syncthreads();
    if (threadIdx.x < W) {
        const int g = b * C + start + threadIdx.x;
        const unsigned sp = s_pred[threadIdx.x], si = s_inter[threadIdx.x], sg = s_gt[threadIdx.x];
        if (sp) atomicAdd(&g_pred[g], sp);
        if (si) atomicAdd(&g_inter[g], si);
        if (sg) atomicAdd(&g_gt[g], sg);
    }
}

template <int TPB, int ITERS>
__global__ void __launch_bounds__(TPB)
seg_hist_fused(const float* __restrict__ logits,
               const int* __restrict__ targets,
               const int* __restrict__ labels,
               float* __restrict__ pred_out,
               float* __restrict__ mean_out,
               int C, int N, int B, int total_blocks)
{
    const int b = blockIdx.y;
    {
        int cls = labels[b];
        cls = min(max(cls, 0), 15);
        const int start = c_starts[cls];
        const int width = c_starts[cls + 1] - start;

        const float* lb = logits + (size_t)b * C * N;
        const int* tb = targets + (size_t)b * N;
        float* pb = pred_out + (size_t)b * N;

        switch (width) {
            case 2: run_body<2, TPB, ITERS>(lb, tb, pb, start, N, b, C); break;
            case 3: run_body<3, TPB, ITERS>(lb, tb, pb, start, N, b, C); break;
            case 4: run_body<4, TPB, ITERS>(lb, tb, pb, start, N, b, C); break;
            default: run_body<6, TPB, ITERS>(lb, tb, pb, start, N, b, C); break;
        }
    }

    // ---- last-block finalize (fused tail) ----
    __shared__ unsigned s_last;
    if (threadIdx.x == 0) {
        __threadfence();                       // publish this block's g_* atomics
        s_last = (atomicAdd(&g_done, 1u) == (unsigned)(total_blocks - 1)) ? 1u : 0u;
    }
    __syncthreads();
    if (!s_last) return;

    __shared__ float s_iou[64];
    const int t = threadIdx.x;
    float v = 0.0f;
    if (t < B) {
        int cls = labels[t];
        cls = min(max(cls, 0), 15);
        const int start = c_starts[cls];
        const int width = c_starts[cls + 1] - start;

        unsigned ci[6], cp[6], cg[6];
#pragma unroll
        for (int j = 0; j < 6; ++j) {
            const int p = start + min(j, width - 1);
            const int g = t * C + p;
            ci[j] = g_inter[g];
            cp[j] = g_pred[g];
            cg[j] = g_gt[g];
        }
        float acc = 0.0f;
#pragma unroll
        for (int j = 0; j < 6; ++j) {
            if (j < width) {
                const float inter = (float)ci[j];
                const float uni = (float)cp[j] + (float)cg[j] - inter;
                acc += (uni == 0.0f) ? 1.0f : (inter / fmaxf(uni, 1.0f));
            }
        }
        v = acc / (float)width;

#pragma unroll
        for (int j = 0; j < 6; ++j) {
            if (j < width) {
                const int g = t * C + start + j;
                g_inter[g] = 0u; g_pred[g] = 0u; g_gt[g] = 0u;   // reset for next replay
            }
        }
    }
    if (t < 64) s_iou[t] = v;
    __syncthreads();
    if (t == 0) {
        float total = 0.0f;
        for (int i = 0; i < B; i++) total += s_iou[i];
        if (mean_out) *mean_out = total / (float)B;
        g_done = 0u;
        __threadfence();
    }
}

// ---------------- fallback (generic sizes): separate kernels ----------------
template <int TPB>
__global__ void __launch_bounds__(TPB)
seg_hist_generic(const float* __restrict__ logits,
                 const int* __restrict__ targets,
                 const int* __restrict__ labels,
                 float* __restrict__ pred_out,
                 int C, int N)
{
    const int b = blockIdx.y;
    int cls = labels[b];
    cls = min(max(cls, 0), 15);
    const int start = c_starts[cls];
    const int width = c_starts[cls + 1] - start;

    __shared__ unsigned s_pred[8], s_gt[8], s_inter[8];
    if (threadIdx.x < 8) { s_pred[threadIdx.x] = 0u; s_gt[threadIdx.x] = 0u; s_inter[threadIdx.x] = 0u; }
    __syncthreads();

    const float* lb = logits + (size_t)b * C * N;
    const int* tb = targets + (size_t)b * N;
    float* pb = pred_out + (size_t)b * N;

    const int pts = (N + gridDim.x - 1) / gridDim.x;
    const int n0 = blockIdx.x * pts;
    const int n1 = min(n0 + pts, N);

    for (int n = n0 + threadIdx.x; n < n1; n += TPB) {
        float best = lb[(size_t)start * N + n];
        int bestc = 0;
        for (int j = 1; j < width; j++) {
            float v = lb[(size_t)(start + j) * N + n];
            if (v > best) { best = v; bestc = j; }
        }
        const unsigned bt = (unsigned)(tb[n] - start);
        atomicAdd(&s_pred[bestc], 1u);
        if (bt == (unsigned)bestc) atomicAdd(&s_inter[bestc], 1u);
        if (bt < (unsigned)width) atomicAdd(&s_gt[bt], 1u);
        pb[n] = (float)(bestc + start);
    }
    __syncthreads();
    if (threadIdx.x < width) {
        const int g = b * C + start + threadIdx.x;
        if (s_pred[threadIdx.x])  atomicAdd(&g_pred[g],  s_pred[threadIdx.x]);
        if (s_gt[threadIdx.x])    atomicAdd(&g_gt[g],    s_gt[threadIdx.x]);
        if (s_inter[threadIdx.x]) atomicAdd(&g_inter[g], s_inter[threadIdx.x]);
    }
}

__global__ void finalize_kernel(const int* __restrict__ labels,
                                float* __restrict__ mean_out,
                                int B, int C)
{
    __shared__ float s_iou[128];
    const int b = threadIdx.x;
    float v = 0.0f;
    if (b < B) {
        int cls = labels[b];
        cls = min(max(cls, 0), 15);
        const int start = c_starts[cls];
        const int end = c_starts[cls + 1];
        float acc = 0.0f;
        for (int p = start; p < end; p++) {
            const int g = b * C + p;
            const float inter = (float)g_inter[g];
            const float uni = (float)g_pred[g] + (float)g_gt[g] - inter;
            const float iou = (uni == 0.0f) ? 1.0f : (inter / fmaxf(uni, 1.0f));
            acc += iou;
            g_inter[g] = 0u; g_pred[g] = 0u; g_gt[g] = 0u;
        }
        v = acc / (float)(end - start);
    }
    if (b < 128) s_iou[b] = v;
    __syncthreads();
    if (threadIdx.x == 0) {
        float total = 0.0f;
        for (int i = 0; i < B; i++) total += s_iou[i];
        if (mean_out) *mean_out = total / (float)B;
    }
}

extern "C" void kernel_launch(void* const* d_in, const int* in_sizes, int n_in,
                              void* d_out, int out_size)
{
    // Identify inputs by element count (labels: B, targets: B*N, logits: B*C*N)
    int i_log = 0, i_lab = 0;
    for (int i = 0; i < 3; i++) {
        if (in_sizes[i] > in_sizes[i_log]) i_log = i;
        if (in_sizes[i] < in_sizes[i_lab]) i_lab = i;
    }
    const int i_tgt = 3 - i_log - i_lab;

    const float* logits  = (const float*)d_in[i_log];
    const int*   targets = (const int*)d_in[i_tgt];
    const int*   labels  = (const int*)d_in[i_lab];

    const int B  = in_sizes[i_lab];
    const int BN = in_sizes[i_tgt];
    const int N  = BN / B;
    const int C  = in_sizes[i_log] / BN;

    float* out = (float*)d_out;
    float* mean_out = nullptr;
    float* pred_out = nullptr;
    if (out_size >= BN + 1)      { mean_out = out; pred_out = out + 1; }
    else if (out_size == BN)     { pred_out = out; }
    else                         { mean_out = out; pred_out = out; }

    constexpr int TPB = 256;
    constexpr int ITERS = 4;                       // 16 points / thread
    const int span = TPB * 4 * ITERS;              // 4096 points / block
    if (pred_out && (N % span) == 0 && B <= 64) {
        dim3 grid(N / span, B);
        const int total_blocks = (N / span) * B;
        seg_hist_fused<TPB, ITERS><<<grid, TPB>>>(logits, targets, labels, pred_out,
                                                  mean_out, C, N, B, total_blocks);
    } else {
        dim3 grid(32, B);
        seg_hist_generic<TPB><<<grid, TPB>>>(logits, targets, labels, pred_out, C, N);
        finalize_kernel<<<1, 128>>>(labels, mean_out, B, C);
    }
}

// round 7
// speedup vs baseline: 2.5339x; 1.0030x over previous
#include <cuda_runtime.h>
#include <cstdint>

__constant__ int c_starts[17] = {0, 4, 6, 8, 12, 16, 19, 22, 24, 28, 30, 36, 38, 41, 44, 47, 50};

#define MAX_BC 4096
__device__ unsigned g_inter[MAX_BC];
__device__ unsigned g_pred[MAX_BC];
__device__ unsigned g_gt[MAX_BC];
__device__ unsigned g_done;   // zero-initialized; reset by last block each run

// ---------------- fast path: streaming argmax, register histograms, low reg pressure --------
// Packed 64-bit accumulators: 6 bins x 10 bits. Per-warp bin sums <= 32*16 = 512 < 1023.
template <int W, int TPB, int ITERS>
__device__ __forceinline__ void run_body(const float* __restrict__ lb,
                                         const int* __restrict__ tb,
                                         float* __restrict__ pb,
                                         int start, int N, int b, int C)
{
    __shared__ unsigned s_gt[8], s_pred[8], s_inter[8];
    if (threadIdx.x < 8) { s_gt[threadIdx.x] = 0u; s_pred[threadIdx.x] = 0u; s_inter[threadIdx.x] = 0u; }

    unsigned long long acc_p = 0ull, acc_i = 0ull, acc_g = 0ull;
    const int tid = threadIdx.x;
    const int base_n = blockIdx.x * (TPB * 4 * ITERS);
    const float* __restrict__ l0 = lb + (size_t)start * N;

#pragma unroll
    for (int it = 0; it < ITERS; ++it) {
        const int n = base_n + (it * TPB + tid) * 4;

        // streaming argmax: only one v4 live at a time -> low register pressure
        float4 best = __ldcs(reinterpret_cast<const float4*>(l0 + n));
        int bc0 = 0, bc1 = 0, bc2 = 0, bc3 = 0;
#pragma unroll
        for (int j = 1; j < W; ++j) {
            const float4 v = __ldcs(reinterpret_cast<const float4*>(l0 + (size_t)j * N + n));
            if (v.x > best.x) { best.x = v.x; bc0 = j; }   // strict > keeps first index on ties
            if (v.y > best.y) { best.y = v.y; bc1 = j; }
            if (v.z > best.z) { best.z = v.z; bc2 = j; }
            if (v.w > best.w) { best.w = v.w; bc3 = j; }
        }
        const int4 t4 = __ldcs(reinterpret_cast<const int4*>(tb + n));

        const int bcs[4]  = {bc0, bc1, bc2, bc3};
        const int tgts[4] = {t4.x, t4.y, t4.z, t4.w};
#pragma unroll
        for (int e = 0; e < 4; ++e) {
            const unsigned bt = (unsigned)(tgts[e] - start);
            const unsigned long long one = 1ull << (bcs[e] * 10);
            acc_p += one;
            if (bt == (unsigned)bcs[e]) acc_i += one;                 // intersection
            if (bt < (unsigned)W) acc_g += 1ull << (bt * 10);         // in-range gt count
            pb[n + e] = (float)(bcs[e] + start);                      // pb may be 4B-offset
        }
    }

    // warp-level reduction of packed accumulators
#pragma unroll
    for (int off = 16; off; off >>= 1) {
        acc_p += __shfl_down_sync(0xFFFFFFFFu, acc_p, off);
        acc_i += __shfl_down_sync(0xFFFFFFFFu, acc_i, off);
        acc_g += __shfl_down_sync(0xFFFFFFFFu, acc_g, off);
    }
    __syncthreads();                          // s_* zeroed before any atomics land
    if ((threadIdx.x & 31) == 0) {
#pragma unroll
        for (int j = 0; j < W; ++j) {
            const unsigned cp = (unsigned)((acc_p >> (10 * j)) & 1023u);
            const unsigned ci = (unsigned)((acc_i >> (10 * j)) & 1023u);
            const unsigned cg = (unsigned)((acc_g >> (10 * j)) & 1023u);
            if (cp) atomicAdd(&s_pred[j], cp);
            if (ci) atomicAdd(&s_inter[j], ci);
            if (cg) atomicAdd(&s_gt[j], cg);
        }
    }
    __syncthreads();
    if (threadIdx.x < W) {
        const int g = b * C + start + threadIdx.x;
        const unsigned sp = s_pred[threadIdx.x], si = s_inter[threadIdx.x], sg = s_gt[threadIdx.x];
        if (sp) atomicAdd(&g_pred[g], sp);
        if (si) atomicAdd(&g_inter[g], si);
        if (sg) atomicAdd(&g_gt[g], sg);
    }
}

template <int TPB, int ITERS>
__global__ void __launch_bounds__(TPB, 6)          // cap regs ~42 -> 6 blocks/SM, 75% occ
seg_hist_fused(const float* __restrict__ logits,
               const int* __restrict__ targets,
               const int* __restrict__ labels,
               float* __restrict__ pred_out,
               float* __restrict__ mean_out,
               int C, int N, int B, int total_blocks)
{
    const int b = blockIdx.y;
    {
        int cls = labels[b];
        cls = min(max(cls, 0), 15);
        const int start = c_starts[cls];
        const int width = c_starts[cls + 1] - start;

        const float* lb = logits + (size_t)b * C * N;
        const int* tb = targets + (size_t)b * N;
        float* pb = pred_out + (size_t)b * N;

        switch (width) {
            case 2: run_body<2, TPB, ITERS>(lb, tb, pb, start, N, b, C); break;
            case 3: run_body<3, TPB, ITERS>(lb, tb, pb, start, N, b, C); break;
            case 4: run_body<4, TPB, ITERS>(lb, tb, pb, start, N, b, C); break;
            default: run_body<6, TPB, ITERS>(lb, tb, pb, start, N, b, C); break;
        }
    }

    // ---- last-block finalize (fused tail) ----
    __shared__ unsigned s_last;
    if (threadIdx.x == 0) {
        __threadfence();                       // publish this block's g_* atomics
        s_last = (atomicAdd(&g_done, 1u) == (unsigned)(total_blocks - 1)) ? 1u : 0u;
    }
    __syncthreads();
    if (!s_last) return;

    __shared__ float s_iou[64];
    const int t = threadIdx.x;
    float v = 0.0f;
    if (t < B) {
        int cls = labels[t];
        cls = min(max(cls, 0), 15);
        const int start = c_starts[cls];
        const int width = c_starts[cls + 1] - start;

        unsigned ci[6], cp[6], cg[6];
#pragma unroll
        for (int j = 0; j < 6; ++j) {
            const int p = start + min(j, width - 1);
            const int g = t * C + p;
            ci[j] = g_inter[g];
            cp[j] = g_pred[g];
            cg[j] = g_gt[g];
        }
        float acc = 0.0f;
#pragma unroll
        for (int j = 0; j < 6; ++j) {
            if (j < width) {
                const float inter = (float)ci[j];
                const float uni = (float)cp[j] + (float)cg[j] - inter;
                acc += (uni == 0.0f) ? 1.0f : (inter / fmaxf(uni, 1.0f));
            }
        }
        v = acc / (float)width;

#pragma unroll
        for (int j = 0; j < 6; ++j) {
            if (j < width) {
                const int g = t * C + start + j;
                g_inter[g] = 0u; g_pred[g] = 0u; g_gt[g] = 0u;   // reset for next replay
            }
        }
    }
    if (t < 64) s_iou[t] = v;
    __syncthreads();
    if (t == 0) {
        float total = 0.0f;
        for (int i = 0; i < B; i++) total += s_iou[i];
        if (mean_out) *mean_out = total / (float)B;
        g_done = 0u;
        __threadfence();
    }
}

// ---------------- fallback (generic sizes): separate kernels ----------------
template <int TPB>
__global__ void __launch_bounds__(TPB)
seg_hist_generic(const float* __restrict__ logits,
                 const int* __restrict__ targets,
                 const int* __restrict__ labels,
                 float* __restrict__ pred_out,
                 int C, int N)
{
    const int b = blockIdx.y;
    int cls = labels[b];
    cls = min(max(cls, 0), 15);
    const int start = c_starts[cls];
    const int width = c_starts[cls + 1] - start;

    __shared__ unsigned s_pred[8], s_gt[8], s_inter[8];
    if (threadIdx.x < 8) { s_pred[threadIdx.x] = 0u; s_gt[threadIdx.x] = 0u; s_inter[threadIdx.x] = 0u; }
    __syncthreads();

    const float* lb = logits + (size_t)b * C * N;
    const int* tb = targets + (size_t)b * N;
    float* pb = pred_out + (size_t)b * N;

    const int pts = (N + gridDim.x - 1) / gridDim.x;
    const int n0 = blockIdx.x * pts;
    const int n1 = min(n0 + pts, N);

    for (int n = n0 + threadIdx.x; n < n1; n += TPB) {
        float best = lb[(size_t)start * N + n];
        int bestc = 0;
        for (int j = 1; j < width; j++) {
            float v = lb[(size_t)(start + j) * N + n];
            if (v > best) { best = v; bestc = j; }
        }
        const unsigned bt = (unsigned)(tb[n] - start);
        atomicAdd(&s_pred[bestc], 1u);
        if (bt == (unsigned)bestc) atomicAdd(&s_inter[bestc], 1u);
        if (bt < (unsigned)width) atomicAdd(&s_gt[bt], 1u);
        pb[n] = (float)(bestc + start);
    }
    __syncthreads();
    if (threadIdx.x < width) {
        const int g = b * C + start + threadIdx.x;
        if (s_pred[threadIdx.x])  atomicAdd(&g_pred[g],  s_pred[threadIdx.x]);
        if (s_gt[threadIdx.x])    atomicAdd(&g_gt[g],    s_gt[threadIdx.x]);
        if (s_inter[threadIdx.x]) atomicAdd(&g_inter[g], s_inter[threadIdx.x]);
    }
}

__global__ void finalize_kernel(const int* __restrict__ labels,
                                float* __restrict__ mean_out,
                                int B, int C)
{
    __shared__ float s_iou[128];
    const int b = threadIdx.x;
    float v = 0.0f;
    if (b < B) {
        int cls = labels[b];
        cls = min(max(cls, 0), 15);
        const int start = c_starts[cls];
        const int end = c_starts[cls + 1];
        float acc = 0.0f;
        for (int p = start; p < end; p++) {
            const int g = b * C + p;
            const float inter = (float)g_inter[g];
            const float uni = (float)g_pred[g] + (float)g_gt[g] - inter;
            const float iou = (uni == 0.0f) ? 1.0f : (inter / fmaxf(uni, 1.0f));
            acc += iou;
            g_inter[g] = 0u; g_pred[g] = 0u; g_gt[g] = 0u;
        }
        v = acc / (float)(end - start);
    }
    if (b < 128) s_iou[b] = v;
    __syncthreads();
    if (threadIdx.x == 0) {
        float total = 0.0f;
        for (int i = 0; i < B; i++) total += s_iou[i];
        if (mean_out) *mean_out = total / (float)B;
    }
}

extern "C" void kernel_launch(void* const* d_in, const int* in_sizes, int n_in,
                              void* d_out, int out_size)
{
    // Identify inputs by element count (labels: B, targets: B*N, logits: B*C*N)
    int i_log = 0, i_lab = 0;
    for (int i = 0; i < 3; i++) {
        if (in_sizes[i] > in_sizes[i_log]) i_log = i;
        if (in_sizes[i] < in_sizes[i_lab]) i_lab = i;
    }
    const int i_tgt = 3 - i_log - i_lab;

    const float* logits  = (const float*)d_in[i_log];
    const int*   targets = (const int*)d_in[i_tgt];
    const int*   labels  = (const int*)d_in[i_lab];

    const int B  = in_sizes[i_lab];
    const int BN = in_sizes[i_tgt];
    const int N  = BN / B;
    const int C  = in_sizes[i_log] / BN;

    float* out = (float*)d_out;
    float* mean_out = nullptr;
    float* pred_out = nullptr;
    if (out_size >= BN + 1)      { mean_out = out; pred_out = out + 1; }
    else if (out_size == BN)     { pred_out = out; }
    else                         { mean_out = out; pred_out = out; }

    constexpr int TPB = 256;
    constexpr int ITERS = 4;                       // 16 points / thread
    const int span = TPB * 4 * ITERS;              // 4096 points / block
    if (pred_out && (N % span) == 0 && B <= 64) {
        dim3 grid(N / span, B);
        const int total_blocks = (N / span) * B;
        seg_hist_fused<TPB, ITERS><<<grid, TPB>>>(logits, targets, labels, pred_out,
                                                  mean_out, C, N, B, total_blocks);
    } else {
        dim3 grid(32, B);
        seg_hist_generic<TPB><<<grid, TPB>>>(logits, targets, labels, pred_out, C, N);
        finalize_kernel<<<1, 128>>>(labels, mean_out, B, C);
    }
}

// round 8
// speedup vs baseline: 2.5378x; 1.0015x over previous
#include <cuda_runtime.h>
#include <cstdint>

__constant__ int c_starts[17] = {0, 4, 6, 8, 12, 16, 19, 22, 24, 28, 30, 36, 38, 41, 44, 47, 50};

#define MAX_BC 4096
__device__ unsigned g_inter[MAX_BC];
__device__ unsigned g_pred[MAX_BC];
__device__ unsigned g_gt[MAX_BC];
__device__ unsigned g_done;   // zero-initialized; reset by last block each run

// ---------------- TMA / mbarrier helpers ----------------
static __device__ __forceinline__ uint32_t smem_u32(const void* p) {
    return (uint32_t)__cvta_generic_to_shared(p);
}
static __device__ __forceinline__ void mbar_init(uint32_t a, uint32_t cnt) {
    asm volatile("mbarrier.init.shared.b64 [%0], %1;" :: "r"(a), "r"(cnt) : "memory");
}
static __device__ __forceinline__ void mbar_expect_tx(uint32_t a, uint32_t bytes) {
    asm volatile("mbarrier.arrive.expect_tx.shared.b64 _, [%0], %1;" :: "r"(a), "r"(bytes) : "memory");
}
static __device__ __forceinline__ void mbar_wait(uint32_t a, uint32_t parity) {
    asm volatile(
        "{\n\t.reg .pred P;\n\t"
        "WL%=:\n\t"
        "mbarrier.try_wait.parity.acquire.cta.shared::cta.b64 P, [%0], %1, 0x989680;\n\t"
        "@P bra WD%=;\n\t"
        "bra WL%=;\n\t"
        "WD%=:\n\t}"
        :: "r"(a), "r"(parity) : "memory");
}
static __device__ __forceinline__ void bulk_g2s(uint32_t dst, const void* src,
                                                uint32_t bytes, uint32_t mbar) {
    asm volatile("cp.async.bulk.shared::cta.global.mbarrier::complete_tx::bytes [%0], [%1], %2, [%3];"
                 :: "r"(dst), "l"(src), "r"(bytes), "r"(mbar) : "memory");
}
static __device__ __forceinline__ void fence_async_shared() {
    asm volatile("fence.proxy.async.shared::cta;" ::: "memory");
}

// ---------------- fast path constants ----------------
constexpr int TPB_F    = 128;
constexpr int TILE_PTS = 512;                 // points per stage
constexpr int TILE_B   = TILE_PTS * 4;        // 2048 B per staged row
constexpr int MAXROWS  = 7;                   // up to 6 logit rows + 1 targets row
constexpr int STAGE_B  = MAXROWS * TILE_B;    // 14336 B per stage
constexpr int STAGES   = 4;
constexpr int SPAN     = TILE_PTS * STAGES;   // 2048 points per block

template <int W>
__device__ __forceinline__ void tma_issue(const float* __restrict__ l0,
                                          const int* __restrict__ tb,
                                          int n0s, uint32_t sb, uint32_t mb, int N)
{
    mbar_expect_tx(mb, (W + 1) * TILE_B);
#pragma unroll
    for (int j = 0; j < W; ++j)
        bulk_g2s(sb + j * TILE_B, l0 + (size_t)j * N + n0s, TILE_B, mb);
    bulk_g2s(sb + W * TILE_B, tb + n0s, TILE_B, mb);
}

// Packed 64-bit accumulators: 6 bins x 10 bits; per-warp bin sums <= 32*16 = 512 < 1023.
template <int W>
__device__ __forceinline__ void fast_body(const float* __restrict__ l0,
                                          const int* __restrict__ tb,
                                          float* __restrict__ pb,
                                          int start, int N, int b, int C, int n0,
                                          const char* sm, uint32_t sm_a, uint32_t mb_a,
                                          unsigned* s_pred, unsigned* s_inter, unsigned* s_gt)
{
    const int tid = threadIdx.x;
    if (tid == 0) {
        tma_issue<W>(l0, tb, n0,            sm_a,           mb_a,     N);
        tma_issue<W>(l0, tb, n0 + TILE_PTS, sm_a + STAGE_B, mb_a + 8, N);
    }

    unsigned long long acc_p = 0ull, acc_i = 0ull, acc_g = 0ull;
#pragma unroll
    for (int s = 0; s < STAGES; ++s) {
        const int p = s & 1;
        mbar_wait(mb_a + p * 8, (s >> 1) & 1);
        const char* sb = sm + p * STAGE_B;
        const int off = tid * 16;

        float4 best = *reinterpret_cast<const float4*>(sb + off);
        int bc0 = 0, bc1 = 0, bc2 = 0, bc3 = 0;
#pragma unroll
        for (int j = 1; j < W; ++j) {
            const float4 v = *reinterpret_cast<const float4*>(sb + j * TILE_B + off);
            if (v.x > best.x) { best.x = v.x; bc0 = j; }   // strict > keeps first index on ties
            if (v.y > best.y) { best.y = v.y; bc1 = j; }
            if (v.z > best.z) { best.z = v.z; bc2 = j; }
            if (v.w > best.w) { best.w = v.w; bc3 = j; }
        }
        const int4 t4 = *reinterpret_cast<const int4*>(sb + W * TILE_B + off);

        const int n = n0 + s * TILE_PTS + tid * 4;
        const int bcs[4] = {bc0, bc1, bc2, bc3};
        const int tg[4]  = {t4.x, t4.y, t4.z, t4.w};
#pragma unroll
        for (int e = 0; e < 4; ++e) {
            const unsigned bt = (unsigned)(tg[e] - start);
            const unsigned long long one = 1ull << (bcs[e] * 10);
            acc_p += one;
            if (bt == (unsigned)bcs[e]) acc_i += one;            // intersection
            if (bt < (unsigned)W) acc_g += 1ull << (bt * 10);    // in-range gt
            pb[n + e] = (float)(bcs[e] + start);                 // pb may be 4B-offset
        }

        __syncthreads();                       // all reads of buffer p done
        if (tid == 0 && s + 2 < STAGES) {
            fence_async_shared();              // order generic reads before async writes
            tma_issue<W>(l0, tb, n0 + (s + 2) * TILE_PTS, sm_a + p * STAGE_B, mb_a + p * 8, N);
        }
    }

    // warp-level reduction of packed accumulators
#pragma unroll
    for (int o = 16; o; o >>= 1) {
        acc_p += __shfl_down_sync(0xFFFFFFFFu, acc_p, o);
        acc_i += __shfl_down_sync(0xFFFFFFFFu, acc_i, o);
        acc_g += __shfl_down_sync(0xFFFFFFFFu, acc_g, o);
    }
    if ((tid & 31) == 0) {
#pragma unroll
        for (int j = 0; j < W; ++j) {
            const unsigned cp = (unsigned)((acc_p >> (10 * j)) & 1023u);
            const unsigned ci = (unsigned)((acc_i >> (10 * j)) & 1023u);
            const unsigned cg = (unsigned)((acc_g >> (10 * j)) & 1023u);
            if (cp) atomicAdd(&s_pred[j], cp);
            if (ci) atomicAdd(&s_inter[j], ci);
            if (cg) atomicAdd(&s_gt[j], cg);
        }
    }
    __syncthreads();
    if (tid < W) {
        const int g = b * C + start + tid;
        const unsigned sp = s_pred[tid], si = s_inter[tid], sg = s_gt[tid];
        if (sp) atomicAdd(&g_pred[g], sp);
        if (si) atomicAdd(&g_inter[g], si);
        if (sg) atomicAdd(&g_gt[g], sg);
    }
}

__global__ void __launch_bounds__(TPB_F)
seg_hist_tma(const float* __restrict__ logits,
             const int* __restrict__ targets,
             const int* __restrict__ labels,
             float* __restrict__ pred_out,
             float* __restrict__ mean_out,
             int C, int N, int B, int total_blocks)
{
    __shared__ __align__(128) char sm[2 * STAGE_B];
    __shared__ __align__(8) unsigned long long mbars[2];
    __shared__ unsigned s_pred[8], s_inter[8], s_gt[8];

    const int tid = threadIdx.x;
    if (tid < 8) { s_pred[tid] = 0u; s_inter[tid] = 0u; s_gt[tid] = 0u; }
    const uint32_t mb_a = smem_u32(mbars);
    const uint32_t sm_a = smem_u32(sm);
    if (tid == 0) { mbar_init(mb_a, 1); mbar_init(mb_a + 8, 1); fence_async_shared(); }
    __syncthreads();

    const int b = blockIdx.y;
    int cls = labels[b];
    cls = min(max(cls, 0), 15);
    const int start = c_starts[cls];
    const int width = c_starts[cls + 1] - start;

    const float* l0 = logits + ((size_t)b * C + start) * N;
    const int* tb = targets + (size_t)b * N;
    float* pb = pred_out + (size_t)b * N;
    const int n0 = blockIdx.x * SPAN;

    switch (width) {
        case 2: fast_body<2>(l0, tb, pb, start, N, b, C, n0, sm, sm_a, mb_a, s_pred, s_inter, s_gt); break;
        case 3: fast_body<3>(l0, tb, pb, start, N, b, C, n0, sm, sm_a, mb_a, s_pred, s_inter, s_gt); break;
        case 4: fast_body<4>(l0, tb, pb, start, N, b, C, n0, sm, sm_a, mb_a, s_pred, s_inter, s_gt); break;
        default: fast_body<6>(l0, tb, pb, start, N, b, C, n0, sm, sm_a, mb_a, s_pred, s_inter, s_gt); break;
    }

    // ---- last-block finalize (fused tail) ----
    __shared__ unsigned s_last;
    if (tid == 0) {
        __threadfence();
        s_last = (atomicAdd(&g_done, 1u) == (unsigned)(total_blocks - 1)) ? 1u : 0u;
    }
    __syncthreads();
    if (!s_last) return;

    __shared__ float s_iou[64];
    float v = 0.0f;
    if (tid < B) {
        int cl = labels[tid];
        cl = min(max(cl, 0), 15);
        const int st = c_starts[cl];
        const int wd = c_starts[cl + 1] - st;

        unsigned ci[6], cp[6], cg[6];
#pragma unroll
        for (int j = 0; j < 6; ++j) {
            const int g = tid * C + st + min(j, wd - 1);
            ci[j] = g_inter[g]; cp[j] = g_pred[g]; cg[j] = g_gt[g];
        }
        float acc = 0.0f;
#pragma unroll
        for (int j = 0; j < 6; ++j) {
            if (j < wd) {
                const float inter = (float)ci[j];
                const float uni = (float)cp[j] + (float)cg[j] - inter;
                acc += (uni == 0.0f) ? 1.0f : (inter / fmaxf(uni, 1.0f));
            }
        }
        v = acc / (float)wd;
#pragma unroll
        for (int j = 0; j < 6; ++j) {
            if (j < wd) {
                const int g = tid * C + st + j;
                g_inter[g] = 0u; g_pred[g] = 0u; g_gt[g] = 0u;   // reset for next replay
            }
        }
    }
    if (tid < 64) s_iou[tid] = v;
    __syncthreads();
    if (tid == 0) {
        float total = 0.0f;
        for (int i = 0; i < B; i++) total += s_iou[i];
        if (mean_out) *mean_out = total / (float)B;
        g_done = 0u;
        __threadfence();
    }
}

// ---------------- fallback (generic sizes): separate kernels ----------------
template <int TPB>
__global__ void __launch_bounds__(TPB)
seg_hist_generic(const float* __restrict__ logits,
                 const int* __restrict__ targets,
                 const int* __restrict__ labels,
                 float* __restrict__ pred_out,
                 int C, int N)
{
    const int b = blockIdx.y;
    int cls = labels[b];
    cls = min(max(cls, 0), 15);
    const int start = c_starts[cls];
    const int width = c_starts[cls + 1] - start;

    __shared__ unsigned s_pred[8], s_gt[8], s_inter[8];
    if (threadIdx.x < 8) { s_pred[threadIdx.x] = 0u; s_gt[threadIdx.x] = 0u; s_inter[threadIdx.x] = 0u; }
    __syncthreads();

    const float* lb = logits + (size_t)b * C * N;
    const int* tb = targets + (size_t)b * N;
    float* pb = pred_out + (size_t)b * N;

    const int pts = (N + gridDim.x - 1) / gridDim.x;
    const int n0 = blockIdx.x * pts;
    const int n1 = min(n0 + pts, N);

    for (int n = n0 + threadIdx.x; n < n1; n += TPB) {
        float best = lb[(size_t)start * N + n];
        int bestc = 0;
        for (int j = 1; j < width; j++) {
            float v = lb[(size_t)(start + j) * N + n];
            if (v > best) { best = v; bestc = j; }
        }
        const unsigned bt = (unsigned)(tb[n] - start);
        atomicAdd(&s_pred[bestc], 1u);
        if (bt == (unsigned)bestc) atomicAdd(&s_inter[bestc], 1u);
        if (bt < (unsigned)width) atomicAdd(&s_gt[bt], 1u);
        pb[n] = (float)(bestc + start);
    }
    __syncthreads();
    if (threadIdx.x < width) {
        const int g = b * C + start + threadIdx.x;
        if (s_pred[threadIdx.x])  atomicAdd(&g_pred[g],  s_pred[threadIdx.x]);
        if (s_gt[threadIdx.x])    atomicAdd(&g_gt[g],    s_gt[threadIdx.x]);
        if (s_inter[threadIdx.x]) atomicAdd(&g_inter[g], s_inter[threadIdx.x]);
    }
}

__global__ void finalize_kernel(const int* __restrict__ labels,
                                float* __restrict__ mean_out,
                                int B, int C)
{
    __shared__ float s_iou[128];
    const int b = threadIdx.x;
    float v = 0.0f;
    if (b < B) {
        int cls = labels[b];
        cls = min(max(cls, 0), 15);
        const int start = c_starts[cls];
        const int end = c_starts[cls + 1];
        float acc = 0.0f;
        for (int p = start; p < end; p++) {
            const int g = b * C + p;
            const float inter = (float)g_inter[g];
            const float uni = (float)g_pred[g] + (float)g_gt[g] - inter;
            const float iou = (uni == 0.0f) ? 1.0f : (inter / fmaxf(uni, 1.0f));
            acc += iou;
            g_inter[g] = 0u; g_pred[g] = 0u; g_gt[g] = 0u;
        }
        v = acc / (float)(end - start);
    }
    if (b < 128) s_iou[b] = v;
    __syncthreads();
    if (threadIdx.x == 0) {
        float total = 0.0f;
        for (int i = 0; i < B; i++) total += s_iou[i];
        if (mean_out) *mean_out = total / (float)B;
    }
}

extern "C" void kernel_launch(void* const* d_in, const int* in_sizes, int n_in,
                              void* d_out, int out_size)
{
    // Identify inputs by element count (labels: B, targets: B*N, logits: B*C*N)
    int i_log = 0, i_lab = 0;
    for (int i = 0; i < 3; i++) {
        if (in_sizes[i] > in_sizes[i_log]) i_log = i;
        if (in_sizes[i] < in_sizes[i_lab]) i_lab = i;
    }
    const int i_tgt = 3 - i_log - i_lab;

    const float* logits  = (const float*)d_in[i_log];
    const int*   targets = (const int*)d_in[i_tgt];
    const int*   labels  = (const int*)d_in[i_lab];

    const int B  = in_sizes[i_lab];
    const int BN = in_sizes[i_tgt];
    const int N  = BN / B;
    const int C  = in_sizes[i_log] / BN;

    float* out = (float*)d_out;
    float* mean_out = nullptr;
    float* pred_out = nullptr;
    if (out_size >= BN + 1)      { mean_out = out; pred_out = out + 1; }
    else if (out_size == BN)     { pred_out = out; }
    else                         { mean_out = out; pred_out = out; }

    if (pred_out && (N % SPAN) == 0 && B <= 64 && B * C <= MAX_BC) {
        dim3 grid(N / SPAN, B);
        const int total_blocks = (N / SPAN) * B;
        seg_hist_tma<<<grid, TPB_F>>>(logits, targets, labels, pred_out,
                                      mean_out, C, N, B, total_blocks);
    } else {
        dim3 grid(32, B);
        seg_hist_generic<256><<<grid, 256>>>(logits, targets, labels, pred_out, C, N);
        finalize_kernel<<<1, 128>>>(labels, mean_out, B, C);
    }
}